// round 15
// baseline (speedup 1.0000x reference)
#include <cuda_runtime.h>
#include <cuda_bf16.h>
#include <cuda_fp16.h>
#include <cstdint>

#define TKN      8192
#define D_DIM    1024
#define E_NUM    8
#define IMOE     1024
#define ISH      4096
#define MAXROWS  17408
#define MAXTILES 136
#define HTILES   68            // MAXTILES/2
#define NSTAGE   3
#define STAGE_SZ 32768          // A 16KB + B 16KB  (tile 128x128, BK=64)
#define SMEM_SZ  (NSTAGE * STAGE_SZ)   // 98304 -> 2 CTAs/SM

// ---------------- helpers ----------------
__device__ __forceinline__ uint32_t smem_u32(const void* p) {
    uint32_t a;
    asm("{ .reg .u64 t; cvta.to.shared.u64 t, %1; cvt.u32.u64 %0, t; }" : "=r"(a) : "l"(p));
    return a;
}
__device__ __forceinline__ void cpa16(uint32_t s, const void* g) {
    asm volatile("cp.async.cg.shared.global [%0], [%1], 16;" :: "r"(s), "l"(g));
}
__device__ __forceinline__ void redadd(float* p, float v) {
    asm volatile("red.global.add.f32 [%0], %1;" :: "l"(p), "f"(v) : "memory");
}
#define CP_COMMIT() asm volatile("cp.async.commit_group;" ::: "memory")
#define CP_WAIT1()  asm volatile("cp.async.wait_group 1;" ::: "memory")

#define LDSM4(R, addr) \
    asm volatile("ldmatrix.sync.aligned.m8n8.x4.shared.b16 {%0,%1,%2,%3}, [%4];" \
        : "=r"((R)[0]), "=r"((R)[1]), "=r"((R)[2]), "=r"((R)[3]) : "r"(addr))

#define MMAF16(C, A, B0, B1) \
    asm volatile("mma.sync.aligned.m16n8k16.row.col.f32.f16.f16.f32 " \
        "{%0,%1,%2,%3},{%4,%5,%6,%7},{%8,%9},{%0,%1,%2,%3};" \
        : "+f"((C)[0]), "+f"((C)[1]), "+f"((C)[2]), "+f"((C)[3]) \
        : "r"((A)[0]), "r"((A)[1]), "r"((A)[2]), "r"((A)[3]), "r"(B0), "r"(B1))

// canonical SW128 swizzle: 128B rows, 8 x 16B groups, XOR by row&7
__device__ __forceinline__ uint32_t swz64(int r, int c8) {
    return (uint32_t)(r * 128 + ((c8 ^ (r & 7)) << 4));
}

// ---------------- device scratch ----------------
__device__ __align__(256) __half g_xs [(size_t)TKN * D_DIM];
__device__ __align__(256) __half g_h  [(size_t)MAXROWS * IMOE];
__device__ __align__(256) __half g_hs [(size_t)TKN * ISH];
__device__ __align__(256) __half g_Bgu [(size_t)E_NUM * 2 * IMOE * D_DIM];
__device__ __align__(256) __half g_Bd  [(size_t)E_NUM * D_DIM * IMOE];
__device__ __align__(256) __half g_Bgsh[(size_t)2 * ISH * D_DIM];
__device__ __align__(256) __half g_Bdsh[(size_t)D_DIM * ISH];

__device__ int   g_counts[E_NUM];
__device__ int   g_fill[E_NUM];
__device__ int   g_offs[E_NUM];
__device__ int   g_topE[2 * TKN];
__device__ float g_topW[2 * TKN];
__device__ float g_sgate[TKN];
__device__ int   g_gatherTok[MAXROWS];
__device__ float g_rowW[MAXROWS];
__device__ int   g_tileExpert[MAXTILES];

// ---------------- small kernels (R13 versions) ----------------
__global__ void zero_meta_kernel() {
    int i = blockIdx.x * blockDim.x + threadIdx.x;
    if (i < MAXROWS) { g_gatherTok[i] = 0; g_rowW[i] = 0.f; }
    if (i < E_NUM) { g_counts[i] = 0; g_fill[i] = 0; }
    if (i < MAXTILES) g_tileExpert[i] = -1;
}

__global__ void zero_out_kernel(float4* __restrict__ o, int n4) {
    int i = blockIdx.x * blockDim.x + threadIdx.x;
    if (i < n4) o[i] = make_float4(0.f, 0.f, 0.f, 0.f);
}

__global__ void fin_kernel() {}

// router: 2 warps per token (each handles 512 of D), smem combine.
// block = 256 threads = 4 tokens. (single isolated change vs R13)
__global__ void router_kernel(const float* __restrict__ x, const float* __restrict__ gw,
                              const float* __restrict__ sgw, float* __restrict__ logits_out,
                              int write_logits, int T) {
    int warp = threadIdx.x >> 5;
    int lane = threadIdx.x & 31;
    int tl   = warp >> 1;          // token-local 0..3
    int half = warp & 1;
    int t = blockIdx.x * 4 + tl;
    bool active = (t < T);

    __shared__ float red[4][2][9];

    float acc[9];
#pragma unroll
    for (int i = 0; i < 9; ++i) acc[i] = 0.f;

    if (active) {
        const float* xr = x + (size_t)t * D_DIM + half * 512;
#pragma unroll
        for (int i = 0; i < 16; ++i) {
            int d = i * 32 + lane;
            float xv = xr[d];
            const float4* g4 = (const float4*)(gw + (size_t)(half * 512 + d) * E_NUM);
            float4 w0 = g4[0], w1 = g4[1];
            acc[0] += xv * w0.x; acc[1] += xv * w0.y; acc[2] += xv * w0.z; acc[3] += xv * w0.w;
            acc[4] += xv * w1.x; acc[5] += xv * w1.y; acc[6] += xv * w1.z; acc[7] += xv * w1.w;
            acc[8] += xv * sgw[half * 512 + d];
        }
#pragma unroll
        for (int o = 16; o; o >>= 1)
#pragma unroll
            for (int i = 0; i < 9; ++i) acc[i] += __shfl_xor_sync(0xffffffffu, acc[i], o);
        if (lane == 0) {
#pragma unroll
            for (int i = 0; i < 9; ++i) red[tl][half][i] = acc[i];
        }
    }
    __syncthreads();
    if (!active || half != 0 || lane != 0) return;

    float l[9];
#pragma unroll
    for (int i = 0; i < 9; ++i) l[i] = red[tl][0][i] + red[tl][1][i];

    float mx = l[0];
#pragma unroll
    for (int e = 1; e < E_NUM; ++e) mx = fmaxf(mx, l[e]);
    float p[E_NUM], s = 0.f;
#pragma unroll
    for (int e = 0; e < E_NUM; ++e) { p[e] = expf(l[e] - mx); s += p[e]; }
    float inv = 1.f / s;
#pragma unroll
    for (int e = 0; e < E_NUM; ++e) p[e] *= inv;
    int i0 = 0;
#pragma unroll
    for (int e = 1; e < E_NUM; ++e) if (p[e] > p[i0]) i0 = e;
    int i1 = (i0 == 0) ? 1 : 0;
#pragma unroll
    for (int e = 0; e < E_NUM; ++e) if (e != i0 && p[e] > p[i1]) i1 = e;
    float w0 = p[i0], w1 = p[i1];
    float invs = 1.f / fmaxf(w0 + w1, 1e-6f);
    g_topE[2 * t] = i0; g_topE[2 * t + 1] = i1;
    g_topW[2 * t] = w0 * invs; g_topW[2 * t + 1] = w1 * invs;
    g_sgate[t] = 1.f / (1.f + expf(-l[8]));
    atomicAdd(&g_counts[i0], 1);
    atomicAdd(&g_counts[i1], 1);
    if (write_logits) {
#pragma unroll
        for (int e = 0; e < E_NUM; ++e)
            logits_out[(size_t)t * E_NUM + e] = l[e];
    }
}

__global__ void scan_kernel() {
    if (threadIdx.x == 0) {
        int s = 0;
        for (int e = 0; e < E_NUM; ++e) {
            g_offs[e] = s;
            int tl = (g_counts[e] + 127) >> 7;
            for (int t = 0; t < tl; ++t) g_tileExpert[(s >> 7) + t] = e;
            s += tl << 7;
        }
    }
}

__global__ void gather_kernel(int T) {
    int t = blockIdx.x * blockDim.x + threadIdx.x;
    if (t >= T) return;
#pragma unroll
    for (int k = 0; k < 2; ++k) {
        int e = g_topE[2 * t + k];
        int p = atomicAdd(&g_fill[e], 1);
        int row = g_offs[e] + p;
        g_gatherTok[row] = t;
        g_rowW[row] = g_topW[2 * t + k];
    }
}

__global__ void convx_kernel(const float* __restrict__ x, __half* __restrict__ xo, int n2) {
    int i = blockIdx.x * blockDim.x + threadIdx.x;
    if (i >= n2) return;
    float2 v = ((const float2*)x)[i];
    ((__half2*)xo)[i] = __floats2half2_rn(v.x, v.y);
}

// weights: src[e][k][n] fp32 -> dst[e][n*rowMul+rowAdd][k] fp16 (R13 32x32 tiles)
__global__ __launch_bounds__(256)
void wtrans_kernel(const float* __restrict__ src, __half* __restrict__ dst,
                   int Ks, int Ns, long long srcE, long long dstE,
                   int rowMul, int rowAdd) {
    src += (long long)blockIdx.z * srcE;
    dst += (long long)blockIdx.z * dstE;
    int tk0 = blockIdx.y * 32, tn0 = blockIdx.x * 32;
    __shared__ float tile[32][33];
    int tx = threadIdx.x & 31, ty = threadIdx.x >> 5;
#pragma unroll
    for (int r = 0; r < 4; ++r) {
        int k = ty + r * 8;
        tile[k][tx] = src[(long long)(tk0 + k) * Ns + tn0 + tx];
    }
    __syncthreads();
    int kk = (threadIdx.x & 7) * 4;
    int nn = threadIdx.x >> 3;
    long long drow = (long long)((tn0 + nn) * rowMul + rowAdd) * Ks + tk0 + kk;
    __align__(8) unsigned short hv[4];
#pragma unroll
    for (int q = 0; q < 4; ++q)
        hv[q] = __half_as_ushort(__float2half(tile[kk + q][nn]));
    *(uint2*)(dst + drow) = *(uint2*)hv;
}

// ---------------- HMMA fp16 GEMM (unchanged from R13) ----------------
// CTA tile 128x128, BK=64, 3-stage cp.async pipeline, 128 threads
// (4 warps 2x2, warp tile 64x64), 2 CTAs/SM. fp32 accumulate.
// MODE 1: adjacent cols (even=gate, odd=up) -> silu(g)*u -> fp16 plane H
// MODE 2: fused combine: red.global.add out[tok*Nout+col] += w*acc
template <int MODE>
__global__ __launch_bounds__(128, 2)
void hgemm(const __half* __restrict__ A, const __half* __restrict__ B,
           long long bStride, float* __restrict__ Cf, __half* __restrict__ H,
           const int* __restrict__ gTok,   // loader A-row gather (or null)
           const int* __restrict__ oTok,   // epilogue row->token (or null)
           const float* __restrict__ rowW, // epilogue row weight (MODE 2)
           const int* __restrict__ tileE,
           int K, int Nout) {
    int e = 0;
    if (tileE) { e = tileE[blockIdx.y]; if (e < 0) return; }
    int rowbase = blockIdx.y * 128;
    int bn = blockIdx.x * 128;
    const char* pA = (const char*)A;
    const char* pB = (const char*)(B + (long long)e * bStride);

    extern __shared__ __align__(1024) char smem[];
    uint32_t sb = smem_u32(smem);
    int tid = threadIdx.x;

    uint32_t aB[8], bB[8], dA[8], dB[8];
#pragma unroll
    for (int i = 0; i < 8; ++i) {
        int q = tid + 128 * i, r = q >> 3, c8 = q & 7;
        int ar = rowbase + r;
        int tok = gTok ? gTok[ar] : ar;
        aB[i] = (uint32_t)((tok * K + c8 * 8) * 2);
        dA[i] = swz64(r, c8);
        bB[i] = (uint32_t)(((bn + r) * K + c8 * 8) * 2);
        dB[i] = 16384 + swz64(r, c8);
    }
    auto issue = [&](int s, int c) {
        uint32_t st = sb + s * STAGE_SZ;
        uint32_t off = (uint32_t)c * 128;
#pragma unroll
        for (int i = 0; i < 8; ++i) cpa16(st + dA[i], pA + aB[i] + off);
#pragma unroll
        for (int i = 0; i < 8; ++i) cpa16(st + dB[i], pB + bB[i] + off);
    };

    int lane = tid & 31, w = tid >> 5;
    int wm = (w & 1) * 64, wn = (w >> 1) * 64;
    uint32_t aA0[4], aB0[4];
    {
        int rowA = wm + (lane & 15);
        int rowB = wn + (lane & 7) + ((lane >> 4) << 3);
#pragma unroll
        for (int h = 0; h < 4; ++h) {
            aA0[h] = swz64(rowA, 2 * h + (lane >> 4));
            aB0[h] = 16384 + swz64(rowB, 2 * h + ((lane >> 3) & 1));
        }
    }

    float acc[4][8][4];
#pragma unroll
    for (int mi = 0; mi < 4; ++mi)
#pragma unroll
        for (int nj = 0; nj < 8; ++nj)
#pragma unroll
            for (int q = 0; q < 4; ++q) acc[mi][nj][q] = 0.f;

    int NC = K >> 6;

    issue(0, 0); CP_COMMIT();
    issue(1, 1); CP_COMMIT();

    int s = 0, ps = 2;
    for (int c = 0; c < NC; ++c) {
        CP_WAIT1();
        __syncthreads();
        int pf = c + 2;
        if (pf < NC) issue(ps, pf);
        CP_COMMIT();
        uint32_t st = sb + s * STAGE_SZ;
#pragma unroll
        for (int h = 0; h < 4; ++h) {
            uint32_t a[4][4], b[8][2];
#pragma unroll
            for (int mi = 0; mi < 4; ++mi) LDSM4(a[mi], st + aA0[h] + mi * 2048);
#pragma unroll
            for (int np = 0; np < 4; ++np) {
                uint32_t q[4];
                LDSM4(q, st + aB0[h] + np * 2048);
                b[2 * np][0] = q[0]; b[2 * np][1] = q[1];
                b[2 * np + 1][0] = q[2]; b[2 * np + 1][1] = q[3];
            }
#pragma unroll
            for (int mi = 0; mi < 4; ++mi)
#pragma unroll
                for (int nj = 0; nj < 8; ++nj)
                    MMAF16(acc[mi][nj], a[mi], b[nj][0], b[nj][1]);
        }
        s = (s == 2) ? 0 : s + 1;
        ps = (ps == 2) ? 0 : ps + 1;
    }

#pragma unroll
    for (int mi = 0; mi < 4; ++mi) {
        int rA = rowbase + wm + mi * 16 + (lane >> 2);
        int rB = rA + 8;
        if (MODE == 1) {
#pragma unroll
            for (int nj = 0; nj < 8; ++nj) {
                int oc = ((bn + wn) >> 1) + nj * 4 + (lane & 3);
                float g0 = acc[mi][nj][0], u0 = acc[mi][nj][1];
                float g1 = acc[mi][nj][2], u1 = acc[mi][nj][3];
                float v0 = g0 / (1.f + expf(-g0)) * u0;
                float v1 = g1 / (1.f + expf(-g1)) * u1;
                H[(size_t)rA * Nout + oc] = __float2half(v0);
                H[(size_t)rB * Nout + oc] = __float2half(v1);
            }
        } else {
            int tokA = oTok ? oTok[rA] : rA;
            int tokB = oTok ? oTok[rB] : rB;
            float wA = rowW[rA], wB = rowW[rB];
            float* oA = Cf + (size_t)tokA * Nout;
            float* oB = Cf + (size_t)tokB * Nout;
#pragma unroll
            for (int nj = 0; nj < 8; ++nj) {
                int col = bn + wn + nj * 8 + (lane & 3) * 2;
                redadd(oA + col,     wA * acc[mi][nj][0]);
                redadd(oA + col + 1, wA * acc[mi][nj][1]);
                redadd(oB + col,     wB * acc[mi][nj][2]);
                redadd(oB + col + 1, wB * acc[mi][nj][3]);
            }
        }
    }
}

// ---------------- launcher: R13 structure exactly ----------------
static cudaStream_t s_sA = 0, s_sB = 0, s_sC = 0;
static cudaEvent_t s_evRoot = 0, s_evX = 0, s_evWsh = 0, s_evMeta = 0,
                   s_evW = 0, s_evZ = 0, s_evA = 0, s_evB = 0, s_evC = 0;
static int s_init_state = 0;

extern "C" void kernel_launch(void* const* d_in, const int* in_sizes, int n_in,
                              void* d_out, int out_size) {
    const float* x   = (const float*)d_in[0];
    const float* gw  = (const float*)d_in[1];
    const float* eg  = (const float*)d_in[2];
    const float* eu  = (const float*)d_in[3];
    const float* ed  = (const float*)d_in[4];
    const float* sg  = (const float*)d_in[5];
    const float* su  = (const float*)d_in[6];
    const float* sd  = (const float*)d_in[7];
    const float* sgw = (const float*)d_in[8];
    float* out = (float*)d_out;
    int T = in_sizes[0] / D_DIM;
    int Th = T / 2;

    __half *xs, *hh, *hs, *bgu, *bd, *bgsh, *bdsh;
    int *gtok, *tileE;
    float *roww, *sgate;
    cudaGetSymbolAddress((void**)&xs, g_xs);
    cudaGetSymbolAddress((void**)&hh, g_h);
    cudaGetSymbolAddress((void**)&hs, g_hs);
    cudaGetSymbolAddress((void**)&bgu, g_Bgu);
    cudaGetSymbolAddress((void**)&bd, g_Bd);
    cudaGetSymbolAddress((void**)&bgsh, g_Bgsh);
    cudaGetSymbolAddress((void**)&bdsh, g_Bdsh);
    cudaGetSymbolAddress((void**)&gtok, g_gatherTok);
    cudaGetSymbolAddress((void**)&roww, g_rowW);
    cudaGetSymbolAddress((void**)&sgate, g_sgate);
    cudaGetSymbolAddress((void**)&tileE, g_tileExpert);

    cudaFuncSetAttribute(hgemm<1>, cudaFuncAttributeMaxDynamicSharedMemorySize, SMEM_SZ);
    cudaFuncSetAttribute(hgemm<2>, cudaFuncAttributeMaxDynamicSharedMemorySize, SMEM_SZ);

    int write_logits = (out_size > T * D_DIM) ? 1 : 0;
    float* logits_out = out + (size_t)T * D_DIM;

    if (s_init_state == 0) {
        bool o = true;
        o = o && (cudaStreamCreateWithFlags(&s_sA, cudaStreamNonBlocking) == cudaSuccess);
        o = o && (cudaStreamCreateWithFlags(&s_sB, cudaStreamNonBlocking) == cudaSuccess);
        o = o && (cudaStreamCreateWithFlags(&s_sC, cudaStreamNonBlocking) == cudaSuccess);
        o = o && (cudaEventCreateWithFlags(&s_evRoot, cudaEventDisableTiming) == cudaSuccess);
        o = o && (cudaEventCreateWithFlags(&s_evX,    cudaEventDisableTiming) == cudaSuccess);
        o = o && (cudaEventCreateWithFlags(&s_evWsh,  cudaEventDisableTiming) == cudaSuccess);
        o = o && (cudaEventCreateWithFlags(&s_evMeta, cudaEventDisableTiming) == cudaSuccess);
        o = o && (cudaEventCreateWithFlags(&s_evW,    cudaEventDisableTiming) == cudaSuccess);
        o = o && (cudaEventCreateWithFlags(&s_evZ,    cudaEventDisableTiming) == cudaSuccess);
        o = o && (cudaEventCreateWithFlags(&s_evA,    cudaEventDisableTiming) == cudaSuccess);
        o = o && (cudaEventCreateWithFlags(&s_evB,    cudaEventDisableTiming) == cudaSuccess);
        o = o && (cudaEventCreateWithFlags(&s_evC,    cudaEventDisableTiming) == cudaSuccess);
        s_init_state = o ? 1 : -1;
    }
    bool ok = (s_init_state == 1);
    cudaStream_t sA = ok ? s_sA : 0, sB = ok ? s_sB : 0, sC = ok ? s_sC : 0;

    if (ok) {
        cudaEventRecord(s_evRoot, 0);
        cudaStreamWaitEvent(sA, s_evRoot, 0);
        cudaStreamWaitEvent(sB, s_evRoot, 0);
        cudaStreamWaitEvent(sC, s_evRoot, 0);
    }

    // ---- s0: zero output token region (REDG target) ----
    zero_out_kernel<<<(T * D_DIM / 4 + 255) / 256, 256>>>((float4*)out, T * D_DIM / 4);
    if (ok) cudaEventRecord(s_evZ, 0);

    // ---- sA: convx ----
    convx_kernel<<<(T * D_DIM / 2 + 255) / 256, 256, 0, sA>>>(x, xs, T * D_DIM / 2);
    if (ok) cudaEventRecord(s_evX, sA);

    // ---- sB: MoE metadata chain ----
    zero_meta_kernel<<<(MAXROWS + 255) / 256, 256, 0, sB>>>();
    router_kernel<<<(T + 3) / 4, 256, 0, sB>>>(x, gw, sgw, logits_out,
                                               write_logits, T);
    scan_kernel<<<1, 32, 0, sB>>>();
    gather_kernel<<<(T + 255) / 256, 256, 0, sB>>>(T);
    if (ok) cudaEventRecord(s_evMeta, sB);

    // ---- sA: shared-expert weight transposes ----
    wtrans_kernel<<<dim3(ISH / 32, D_DIM / 32, 1), 256, 0, sA>>>(
        sg, bgsh, D_DIM, ISH, 0, 0, 2, 0);
    wtrans_kernel<<<dim3(ISH / 32, D_DIM / 32, 1), 256, 0, sA>>>(
        su, bgsh, D_DIM, ISH, 0, 0, 2, 1);
    wtrans_kernel<<<dim3(D_DIM / 32, ISH / 32, 1), 256, 0, sA>>>(
        sd, bdsh, ISH, D_DIM, 0, 0, 1, 0);
    if (ok) cudaEventRecord(s_evWsh, sA);

    // ---- s0: MoE weight transposes ----
    wtrans_kernel<<<dim3(IMOE / 32, D_DIM / 32, E_NUM), 256>>>(
        eg, bgu, D_DIM, IMOE, (long long)D_DIM * IMOE, 2LL * IMOE * D_DIM, 2, 0);
    wtrans_kernel<<<dim3(IMOE / 32, D_DIM / 32, E_NUM), 256>>>(
        eu, bgu, D_DIM, IMOE, (long long)D_DIM * IMOE, 2LL * IMOE * D_DIM, 2, 1);
    wtrans_kernel<<<dim3(D_DIM / 32, IMOE / 32, E_NUM), 256>>>(
        ed, bd, IMOE, D_DIM, (long long)IMOE * D_DIM, (long long)D_DIM * IMOE, 1, 0);
    if (ok) cudaEventRecord(s_evW, 0);

    // ---- GU GEMMs (4 half-chains, tile N=128, 128 threads) ----
    hgemm<1><<<dim3(2 * ISH / 128, Th / 128), 128, SMEM_SZ, sA>>>(
        xs, bgsh, 0, nullptr, hs, nullptr, nullptr, nullptr, nullptr, D_DIM, ISH);
    if (ok) cudaStreamWaitEvent(sC, s_evWsh, 0);   // implies convx done (sA order)
    hgemm<1><<<dim3(2 * ISH / 128, Th / 128), 128, SMEM_SZ, sC>>>(
        xs + (size_t)Th * D_DIM, bgsh, 0, nullptr, hs + (size_t)Th * ISH,
        nullptr, nullptr, nullptr, nullptr, D_DIM, ISH);
    if (ok) { cudaStreamWaitEvent(0, s_evMeta, 0); cudaStreamWaitEvent(0, s_evX, 0); }
    hgemm<1><<<dim3(2 * IMOE / 128, HTILES), 128, SMEM_SZ>>>(
        xs, bgu, 2LL * IMOE * D_DIM, nullptr, hh, gtok, nullptr, nullptr,
        tileE, D_DIM, IMOE);
    if (ok) { cudaStreamWaitEvent(sB, s_evW, 0); cudaStreamWaitEvent(sB, s_evX, 0); }
    hgemm<1><<<dim3(2 * IMOE / 128, HTILES), 128, SMEM_SZ, sB>>>(
        xs, bgu, 2LL * IMOE * D_DIM, nullptr, hh + (size_t)HTILES * 128 * IMOE,
        gtok + HTILES * 128, nullptr, nullptr, tileE + HTILES, D_DIM, IMOE);

    // ---- down GEMMs (4 half-chains, fused weighted scatter-add into out) ----
    if (ok) cudaStreamWaitEvent(sA, s_evZ, 0);
    hgemm<2><<<dim3(D_DIM / 128, Th / 128), 128, SMEM_SZ, sA>>>(
        hs, bdsh, 0, out, nullptr, nullptr, nullptr, sgate, nullptr, ISH, D_DIM);
    if (ok) cudaEventRecord(s_evA, sA);
    if (ok) cudaStreamWaitEvent(sC, s_evZ, 0);
    hgemm<2><<<dim3(D_DIM / 128, Th / 128), 128, SMEM_SZ, sC>>>(
        hs + (size_t)Th * ISH, bdsh, 0, out + (size_t)Th * D_DIM, nullptr,
        nullptr, nullptr, sgate + Th, nullptr, ISH, D_DIM);
    if (ok) cudaEventRecord(s_evC, sC);
    hgemm<2><<<dim3(D_DIM / 128, HTILES), 128, SMEM_SZ>>>(
        hh, bd, (long long)D_DIM * IMOE, out, nullptr,
        nullptr, gtok, roww, tileE, IMOE, D_DIM);
    if (ok) cudaStreamWaitEvent(sB, s_evZ, 0);
    hgemm<2><<<dim3(D_DIM / 128, HTILES), 128, SMEM_SZ, sB>>>(
        hh + (size_t)HTILES * 128 * IMOE, bd, (long long)D_DIM * IMOE, out, nullptr,
        nullptr, gtok + HTILES * 128, roww + HTILES * 128, tileE + HTILES,
        IMOE, D_DIM);
    if (ok) cudaEventRecord(s_evB, sB);

    // ---- join back to s0 (graph-capture requires rejoining side streams) ----
    if (ok) {
        cudaStreamWaitEvent(0, s_evA, 0);
        cudaStreamWaitEvent(0, s_evB, 0);
        cudaStreamWaitEvent(0, s_evC, 0);
    }
    fin_kernel<<<1, 32>>>();
}

// round 16
// speedup vs baseline: 1.5165x; 1.5165x over previous
#include <cuda_runtime.h>
#include <cuda_bf16.h>
#include <cuda_fp16.h>
#include <cstdint>

#define TKN      8192
#define D_DIM    1024
#define E_NUM    8
#define IMOE     1024
#define ISH      4096
#define MAXROWS  17408
#define MAXTILES 136
#define HTILES   68            // MAXTILES/2
#define NSTAGE   3
#define STAGE_SZ 32768          // A 16KB + B 16KB  (tile 128x128, BK=64)
#define SMEM_SZ  (NSTAGE * STAGE_SZ)   // 98304 -> 2 CTAs/SM

// ---------------- helpers ----------------
__device__ __forceinline__ uint32_t smem_u32(const void* p) {
    uint32_t a;
    asm("{ .reg .u64 t; cvta.to.shared.u64 t, %1; cvt.u32.u64 %0, t; }" : "=r"(a) : "l"(p));
    return a;
}
__device__ __forceinline__ void cpa16(uint32_t s, const void* g) {
    asm volatile("cp.async.cg.shared.global [%0], [%1], 16;" :: "r"(s), "l"(g));
}
__device__ __forceinline__ void redadd(float* p, float v) {
    asm volatile("red.global.add.f32 [%0], %1;" :: "l"(p), "f"(v) : "memory");
}
#define CP_COMMIT() asm volatile("cp.async.commit_group;" ::: "memory")
#define CP_WAIT1()  asm volatile("cp.async.wait_group 1;" ::: "memory")

#define LDSM4(R, addr) \
    asm volatile("ldmatrix.sync.aligned.m8n8.x4.shared.b16 {%0,%1,%2,%3}, [%4];" \
        : "=r"((R)[0]), "=r"((R)[1]), "=r"((R)[2]), "=r"((R)[3]) : "r"(addr))

#define MMAF16(C, A, B0, B1) \
    asm volatile("mma.sync.aligned.m16n8k16.row.col.f32.f16.f16.f32 " \
        "{%0,%1,%2,%3},{%4,%5,%6,%7},{%8,%9},{%0,%1,%2,%3};" \
        : "+f"((C)[0]), "+f"((C)[1]), "+f"((C)[2]), "+f"((C)[3]) \
        : "r"((A)[0]), "r"((A)[1]), "r"((A)[2]), "r"((A)[3]), "r"(B0), "r"(B1))

// canonical SW128 swizzle: 128B rows, 8 x 16B groups, XOR by row&7
__device__ __forceinline__ uint32_t swz64(int r, int c8) {
    return (uint32_t)(r * 128 + ((c8 ^ (r & 7)) << 4));
}

// ---------------- device scratch ----------------
__device__ __align__(256) __half g_xs [(size_t)TKN * D_DIM];
__device__ __align__(256) __half g_h  [(size_t)MAXROWS * IMOE];
__device__ __align__(256) __half g_hs [(size_t)TKN * ISH];
__device__ __align__(256) __half g_Bgu [(size_t)E_NUM * 2 * IMOE * D_DIM];
__device__ __align__(256) __half g_Bd  [(size_t)E_NUM * D_DIM * IMOE];
__device__ __align__(256) __half g_Bgsh[(size_t)2 * ISH * D_DIM];
__device__ __align__(256) __half g_Bdsh[(size_t)D_DIM * ISH];

__device__ int   g_counts[E_NUM];
__device__ int   g_fill[E_NUM];
__device__ int   g_offs[E_NUM];
__device__ int   g_topE[2 * TKN];
__device__ float g_topW[2 * TKN];
__device__ float g_sgate[TKN];
__device__ int   g_gatherTok[MAXROWS];
__device__ float g_rowW[MAXROWS];
__device__ int   g_tileExpert[MAXTILES];

// ---------------- small kernels ----------------
__global__ void zero_meta_kernel() {
    int i = blockIdx.x * blockDim.x + threadIdx.x;
    if (i < MAXROWS) { g_gatherTok[i] = 0; g_rowW[i] = 0.f; }
    if (i < E_NUM) { g_counts[i] = 0; g_fill[i] = 0; }
    if (i < MAXTILES) g_tileExpert[i] = -1;
}

__global__ void zero_out_kernel(float4* __restrict__ o, int n4) {
    int i = blockIdx.x * blockDim.x + threadIdx.x;
    if (i < n4) o[i] = make_float4(0.f, 0.f, 0.f, 0.f);
}

__global__ void fin_kernel() {}

// router: one warp per token (R13 version)
__global__ void router_kernel(const float* __restrict__ x, const float* __restrict__ gw,
                              const float* __restrict__ sgw, float* __restrict__ logits_out,
                              int write_logits, int T) {
    int gwarp = (blockIdx.x * blockDim.x + threadIdx.x) >> 5;
    int lane  = threadIdx.x & 31;
    if (gwarp >= T) return;
    const float* xr = x + (size_t)gwarp * D_DIM;
    float acc[9];
#pragma unroll
    for (int i = 0; i < 9; ++i) acc[i] = 0.f;
    for (int d = lane; d < D_DIM; d += 32) {
        float xv = xr[d];
        const float4* g4 = (const float4*)(gw + (size_t)d * E_NUM);
        float4 w0 = g4[0], w1 = g4[1];
        acc[0] += xv * w0.x; acc[1] += xv * w0.y; acc[2] += xv * w0.z; acc[3] += xv * w0.w;
        acc[4] += xv * w1.x; acc[5] += xv * w1.y; acc[6] += xv * w1.z; acc[7] += xv * w1.w;
        acc[8] += xv * sgw[d];
    }
#pragma unroll
    for (int o = 16; o; o >>= 1)
#pragma unroll
        for (int i = 0; i < 9; ++i) acc[i] += __shfl_xor_sync(0xffffffffu, acc[i], o);
    if (lane == 0) {
        float mx = acc[0];
#pragma unroll
        for (int e = 1; e < E_NUM; ++e) mx = fmaxf(mx, acc[e]);
        float p[E_NUM], s = 0.f;
#pragma unroll
        for (int e = 0; e < E_NUM; ++e) { p[e] = expf(acc[e] - mx); s += p[e]; }
        float inv = 1.f / s;
#pragma unroll
        for (int e = 0; e < E_NUM; ++e) p[e] *= inv;
        int i0 = 0;
#pragma unroll
        for (int e = 1; e < E_NUM; ++e) if (p[e] > p[i0]) i0 = e;
        int i1 = (i0 == 0) ? 1 : 0;
#pragma unroll
        for (int e = 0; e < E_NUM; ++e) if (e != i0 && p[e] > p[i1]) i1 = e;
        float w0 = p[i0], w1 = p[i1];
        float invs = 1.f / fmaxf(w0 + w1, 1e-6f);
        g_topE[2 * gwarp] = i0; g_topE[2 * gwarp + 1] = i1;
        g_topW[2 * gwarp] = w0 * invs; g_topW[2 * gwarp + 1] = w1 * invs;
        g_sgate[gwarp] = 1.f / (1.f + expf(-acc[8]));
        atomicAdd(&g_counts[i0], 1);
        atomicAdd(&g_counts[i1], 1);
        if (write_logits) {
#pragma unroll
            for (int e = 0; e < E_NUM; ++e)
                logits_out[(size_t)gwarp * E_NUM + e] = acc[e];
        }
    }
}

__global__ void scan_kernel() {
    if (threadIdx.x == 0) {
        int s = 0;
        for (int e = 0; e < E_NUM; ++e) {
            g_offs[e] = s;
            int tl = (g_counts[e] + 127) >> 7;
            for (int t = 0; t < tl; ++t) g_tileExpert[(s >> 7) + t] = e;
            s += tl << 7;
        }
    }
}

__global__ void gather_kernel(int T) {
    int t = blockIdx.x * blockDim.x + threadIdx.x;
    if (t >= T) return;
#pragma unroll
    for (int k = 0; k < 2; ++k) {
        int e = g_topE[2 * t + k];
        int p = atomicAdd(&g_fill[e], 1);
        int row = g_offs[e] + p;
        g_gatherTok[row] = t;
        g_rowW[row] = g_topW[2 * t + k];
    }
}

__global__ void convx_kernel(const float* __restrict__ x, __half* __restrict__ xo, int n2) {
    int i = blockIdx.x * blockDim.x + threadIdx.x;
    if (i >= n2) return;
    float2 v = ((const float2*)x)[i];
    ((__half2*)xo)[i] = __floats2half2_rn(v.x, v.y);
}

// weights: src[e][k][n] fp32 -> dst[e][n*rowMul+rowAdd][k] fp16 (k-major rows)
__global__ __launch_bounds__(256)
void wtrans_kernel(const float* __restrict__ src, __half* __restrict__ dst,
                   int Ks, int Ns, long long srcE, long long dstE,
                   int rowMul, int rowAdd) {
    src += (long long)blockIdx.z * srcE;
    dst += (long long)blockIdx.z * dstE;
    int tk0 = blockIdx.y * 32, tn0 = blockIdx.x * 32;
    __shared__ float tile[32][33];
    int tx = threadIdx.x & 31, ty = threadIdx.x >> 5;
#pragma unroll
    for (int r = 0; r < 4; ++r) {
        int k = ty + r * 8;
        tile[k][tx] = src[(long long)(tk0 + k) * Ns + tn0 + tx];
    }
    __syncthreads();
    int kk = (threadIdx.x & 7) * 4;
    int nn = threadIdx.x >> 3;
    long long drow = (long long)((tn0 + nn) * rowMul + rowAdd) * Ks + tk0 + kk;
    __align__(8) unsigned short hv[4];
#pragma unroll
    for (int q = 0; q < 4; ++q)
        hv[q] = __half_as_ushort(__float2half(tile[kk + q][nn]));
    *(uint2*)(dst + drow) = *(uint2*)hv;
}

// ---------------- HMMA fp16 GEMM ----------------
// CTA tile 128x128, BK=64, 3-stage cp.async pipeline, 128 threads
// (4 warps 2x2, warp tile 64x64), 2 CTAs/SM. fp32 accumulate.
// MODE 1: adjacent cols (even=gate, odd=up) -> silu(g)*u -> fp16 plane H
// MODE 2: fused combine: red.global.add out[tok*Nout+col] += w*acc
template <int MODE>
__global__ __launch_bounds__(128, 2)
void hgemm(const __half* __restrict__ A, const __half* __restrict__ B,
           long long bStride, float* __restrict__ Cf, __half* __restrict__ H,
           const int* __restrict__ gTok,   // loader A-row gather (or null)
           const int* __restrict__ oTok,   // epilogue row->token (or null)
           const float* __restrict__ rowW, // epilogue row weight (MODE 2)
           const int* __restrict__ tileE,
           int K, int Nout) {
    int e = 0;
    if (tileE) { e = tileE[blockIdx.y]; if (e < 0) return; }
    int rowbase = blockIdx.y * 128;
    int bn = blockIdx.x * 128;
    const char* pA = (const char*)A;
    const char* pB = (const char*)(B + (long long)e * bStride);

    extern __shared__ __align__(1024) char smem[];
    uint32_t sb = smem_u32(smem);
    int tid = threadIdx.x;

    uint32_t aB[8], bB[8], dA[8], dB[8];
#pragma unroll
    for (int i = 0; i < 8; ++i) {
        int q = tid + 128 * i, r = q >> 3, c8 = q & 7;
        int ar = rowbase + r;
        int tok = gTok ? gTok[ar] : ar;
        aB[i] = (uint32_t)((tok * K + c8 * 8) * 2);
        dA[i] = swz64(r, c8);
        bB[i] = (uint32_t)(((bn + r) * K + c8 * 8) * 2);
        dB[i] = 16384 + swz64(r, c8);
    }
    auto issue = [&](int s, int c) {
        uint32_t st = sb + s * STAGE_SZ;
        uint32_t off = (uint32_t)c * 128;
#pragma unroll
        for (int i = 0; i < 8; ++i) cpa16(st + dA[i], pA + aB[i] + off);
#pragma unroll
        for (int i = 0; i < 8; ++i) cpa16(st + dB[i], pB + bB[i] + off);
    };

    int lane = tid & 31, w = tid >> 5;
    int wm = (w & 1) * 64, wn = (w >> 1) * 64;
    uint32_t aA0[4], aB0[4];
    {
        int rowA = wm + (lane & 15);
        int rowB = wn + (lane & 7) + ((lane >> 4) << 3);
#pragma unroll
        for (int h = 0; h < 4; ++h) {
            aA0[h] = swz64(rowA, 2 * h + (lane >> 4));
            aB0[h] = 16384 + swz64(rowB, 2 * h + ((lane >> 3) & 1));
        }
    }

    float acc[4][8][4];
#pragma unroll
    for (int mi = 0; mi < 4; ++mi)
#pragma unroll
        for (int nj = 0; nj < 8; ++nj)
#pragma unroll
            for (int q = 0; q < 4; ++q) acc[mi][nj][q] = 0.f;

    int NC = K >> 6;

    issue(0, 0); CP_COMMIT();
    issue(1, 1); CP_COMMIT();

    int s = 0, ps = 2;
    for (int c = 0; c < NC; ++c) {
        CP_WAIT1();
        __syncthreads();
        int pf = c + 2;
        if (pf < NC) issue(ps, pf);
        CP_COMMIT();
        uint32_t st = sb + s * STAGE_SZ;
#pragma unroll
        for (int h = 0; h < 4; ++h) {
            uint32_t a[4][4], b[8][2];
#pragma unroll
            for (int mi = 0; mi < 4; ++mi) LDSM4(a[mi], st + aA0[h] + mi * 2048);
#pragma unroll
            for (int np = 0; np < 4; ++np) {
                uint32_t q[4];
                LDSM4(q, st + aB0[h] + np * 2048);
                b[2 * np][0] = q[0]; b[2 * np][1] = q[1];
                b[2 * np + 1][0] = q[2]; b[2 * np + 1][1] = q[3];
            }
#pragma unroll
            for (int mi = 0; mi < 4; ++mi)
#pragma unroll
                for (int nj = 0; nj < 8; ++nj)
                    MMAF16(acc[mi][nj], a[mi], b[nj][0], b[nj][1]);
        }
        s = (s == 2) ? 0 : s + 1;
        ps = (ps == 2) ? 0 : ps + 1;
    }

#pragma unroll
    for (int mi = 0; mi < 4; ++mi) {
        int rA = rowbase + wm + mi * 16 + (lane >> 2);
        int rB = rA + 8;
        if (MODE == 1) {
#pragma unroll
            for (int nj = 0; nj < 8; ++nj) {
                int oc = ((bn + wn) >> 1) + nj * 4 + (lane & 3);
                float g0 = acc[mi][nj][0], u0 = acc[mi][nj][1];
                float g1 = acc[mi][nj][2], u1 = acc[mi][nj][3];
                float v0 = g0 / (1.f + expf(-g0)) * u0;
                float v1 = g1 / (1.f + expf(-g1)) * u1;
                H[(size_t)rA * Nout + oc] = __float2half(v0);
                H[(size_t)rB * Nout + oc] = __float2half(v1);
            }
        } else {
            int tokA = oTok ? oTok[rA] : rA;
            int tokB = oTok ? oTok[rB] : rB;
            float wA = rowW[rA], wB = rowW[rB];
            float* oA = Cf + (size_t)tokA * Nout;
            float* oB = Cf + (size_t)tokB * Nout;
#pragma unroll
            for (int nj = 0; nj < 8; ++nj) {
                int col = bn + wn + nj * 8 + (lane & 3) * 2;
                redadd(oA + col,     wA * acc[mi][nj][0]);
                redadd(oA + col + 1, wA * acc[mi][nj][1]);
                redadd(oB + col,     wB * acc[mi][nj][2]);
                redadd(oB + col + 1, wB * acc[mi][nj][3]);
            }
        }
    }
}

// ---------------- launcher: R13 structure exactly ----------------
static cudaStream_t s_sA = 0, s_sB = 0, s_sC = 0;
static cudaEvent_t s_evRoot = 0, s_evX = 0, s_evWsh = 0, s_evMeta = 0,
                   s_evW = 0, s_evZ = 0, s_evA = 0, s_evB = 0, s_evC = 0;
static int s_init_state = 0;

extern "C" void kernel_launch(void* const* d_in, const int* in_sizes, int n_in,
                              void* d_out, int out_size) {
    const float* x   = (const float*)d_in[0];
    const float* gw  = (const float*)d_in[1];
    const float* eg  = (const float*)d_in[2];
    const float* eu  = (const float*)d_in[3];
    const float* ed  = (const float*)d_in[4];
    const float* sg  = (const float*)d_in[5];
    const float* su  = (const float*)d_in[6];
    const float* sd  = (const float*)d_in[7];
    const float* sgw = (const float*)d_in[8];
    float* out = (float*)d_out;
    int T = in_sizes[0] / D_DIM;
    int Th = T / 2;

    __half *xs, *hh, *hs, *bgu, *bd, *bgsh, *bdsh;
    int *gtok, *tileE;
    float *roww, *sgate;
    cudaGetSymbolAddress((void**)&xs, g_xs);
    cudaGetSymbolAddress((void**)&hh, g_h);
    cudaGetSymbolAddress((void**)&hs, g_hs);
    cudaGetSymbolAddress((void**)&bgu, g_Bgu);
    cudaGetSymbolAddress((void**)&bd, g_Bd);
    cudaGetSymbolAddress((void**)&bgsh, g_Bgsh);
    cudaGetSymbolAddress((void**)&bdsh, g_Bdsh);
    cudaGetSymbolAddress((void**)&gtok, g_gatherTok);
    cudaGetSymbolAddress((void**)&roww, g_rowW);
    cudaGetSymbolAddress((void**)&sgate, g_sgate);
    cudaGetSymbolAddress((void**)&tileE, g_tileExpert);

    cudaFuncSetAttribute(hgemm<1>, cudaFuncAttributeMaxDynamicSharedMemorySize, SMEM_SZ);
    cudaFuncSetAttribute(hgemm<2>, cudaFuncAttributeMaxDynamicSharedMemorySize, SMEM_SZ);

    int write_logits = (out_size > T * D_DIM) ? 1 : 0;
    float* logits_out = out + (size_t)T * D_DIM;

    if (s_init_state == 0) {
        bool o = true;
        o = o && (cudaStreamCreateWithFlags(&s_sA, cudaStreamNonBlocking) == cudaSuccess);
        o = o && (cudaStreamCreateWithFlags(&s_sB, cudaStreamNonBlocking) == cudaSuccess);
        o = o && (cudaStreamCreateWithFlags(&s_sC, cudaStreamNonBlocking) == cudaSuccess);
        o = o && (cudaEventCreateWithFlags(&s_evRoot, cudaEventDisableTiming) == cudaSuccess);
        o = o && (cudaEventCreateWithFlags(&s_evX,    cudaEventDisableTiming) == cudaSuccess);
        o = o && (cudaEventCreateWithFlags(&s_evWsh,  cudaEventDisableTiming) == cudaSuccess);
        o = o && (cudaEventCreateWithFlags(&s_evMeta, cudaEventDisableTiming) == cudaSuccess);
        o = o && (cudaEventCreateWithFlags(&s_evW,    cudaEventDisableTiming) == cudaSuccess);
        o = o && (cudaEventCreateWithFlags(&s_evZ,    cudaEventDisableTiming) == cudaSuccess);
        o = o && (cudaEventCreateWithFlags(&s_evA,    cudaEventDisableTiming) == cudaSuccess);
        o = o && (cudaEventCreateWithFlags(&s_evB,    cudaEventDisableTiming) == cudaSuccess);
        o = o && (cudaEventCreateWithFlags(&s_evC,    cudaEventDisableTiming) == cudaSuccess);
        s_init_state = o ? 1 : -1;
    }
    bool ok = (s_init_state == 1);
    cudaStream_t sA = ok ? s_sA : 0, sB = ok ? s_sB : 0, sC = ok ? s_sC : 0;

    if (ok) {
        cudaEventRecord(s_evRoot, 0);
        cudaStreamWaitEvent(sA, s_evRoot, 0);
        cudaStreamWaitEvent(sB, s_evRoot, 0);
        cudaStreamWaitEvent(sC, s_evRoot, 0);
    }

    // ---- s0: zero output token region (REDG target) ----
    zero_out_kernel<<<(T * D_DIM / 4 + 255) / 256, 256>>>((float4*)out, T * D_DIM / 4);
    if (ok) cudaEventRecord(s_evZ, 0);

    // ---- sA: convx ----
    convx_kernel<<<(T * D_DIM / 2 + 255) / 256, 256, 0, sA>>>(x, xs, T * D_DIM / 2);
    if (ok) cudaEventRecord(s_evX, sA);

    // ---- sB: MoE metadata chain ----
    zero_meta_kernel<<<(MAXROWS + 255) / 256, 256, 0, sB>>>();
    router_kernel<<<(T * 32 + 255) / 256, 256, 0, sB>>>(x, gw, sgw, logits_out,
                                                        write_logits, T);
    scan_kernel<<<1, 32, 0, sB>>>();
    gather_kernel<<<(T + 255) / 256, 256, 0, sB>>>(T);
    if (ok) cudaEventRecord(s_evMeta, sB);

    // ---- sA: shared-expert weight transposes ----
    wtrans_kernel<<<dim3(ISH / 32, D_DIM / 32, 1), 256, 0, sA>>>(
        sg, bgsh, D_DIM, ISH, 0, 0, 2, 0);
    wtrans_kernel<<<dim3(ISH / 32, D_DIM / 32, 1), 256, 0, sA>>>(
        su, bgsh, D_DIM, ISH, 0, 0, 2, 1);
    wtrans_kernel<<<dim3(D_DIM / 32, ISH / 32, 1), 256, 0, sA>>>(
        sd, bdsh, ISH, D_DIM, 0, 0, 1, 0);
    if (ok) cudaEventRecord(s_evWsh, sA);

    // ---- s0: MoE weight transposes ----
    wtrans_kernel<<<dim3(IMOE / 32, D_DIM / 32, E_NUM), 256>>>(
        eg, bgu, D_DIM, IMOE, (long long)D_DIM * IMOE, 2LL * IMOE * D_DIM, 2, 0);
    wtrans_kernel<<<dim3(IMOE / 32, D_DIM / 32, E_NUM), 256>>>(
        eu, bgu, D_DIM, IMOE, (long long)D_DIM * IMOE, 2LL * IMOE * D_DIM, 2, 1);
    wtrans_kernel<<<dim3(D_DIM / 32, IMOE / 32, E_NUM), 256>>>(
        ed, bd, IMOE, D_DIM, (long long)IMOE * D_DIM, (long long)D_DIM * IMOE, 1, 0);
    if (ok) cudaEventRecord(s_evW, 0);

    // ---- GU GEMMs (4 half-chains, tile N=128, 128 threads) ----
    hgemm<1><<<dim3(2 * ISH / 128, Th / 128), 128, SMEM_SZ, sA>>>(
        xs, bgsh, 0, nullptr, hs, nullptr, nullptr, nullptr, nullptr, D_DIM, ISH);
    if (ok) cudaStreamWaitEvent(sC, s_evWsh, 0);   // implies convx done (sA order)
    hgemm<1><<<dim3(2 * ISH / 128, Th / 128), 128, SMEM_SZ, sC>>>(
        xs + (size_t)Th * D_DIM, bgsh, 0, nullptr, hs + (size_t)Th * ISH,
        nullptr, nullptr, nullptr, nullptr, D_DIM, ISH);
    if (ok) { cudaStreamWaitEvent(0, s_evMeta, 0); cudaStreamWaitEvent(0, s_evX, 0); }
    hgemm<1><<<dim3(2 * IMOE / 128, HTILES), 128, SMEM_SZ>>>(
        xs, bgu, 2LL * IMOE * D_DIM, nullptr, hh, gtok, nullptr, nullptr,
        tileE, D_DIM, IMOE);
    if (ok) { cudaStreamWaitEvent(sB, s_evW, 0); cudaStreamWaitEvent(sB, s_evX, 0); }
    hgemm<1><<<dim3(2 * IMOE / 128, HTILES), 128, SMEM_SZ, sB>>>(
        xs, bgu, 2LL * IMOE * D_DIM, nullptr, hh + (size_t)HTILES * 128 * IMOE,
        gtok + HTILES * 128, nullptr, nullptr, tileE + HTILES, D_DIM, IMOE);

    // ---- down GEMMs (4 half-chains, fused weighted scatter-add into out) ----
    if (ok) cudaStreamWaitEvent(sA, s_evZ, 0);
    hgemm<2><<<dim3(D_DIM / 128, Th / 128), 128, SMEM_SZ, sA>>>(
        hs, bdsh, 0, out, nullptr, nullptr, nullptr, sgate, nullptr, ISH, D_DIM);
    if (ok) cudaEventRecord(s_evA, sA);
    if (ok) cudaStreamWaitEvent(sC, s_evZ, 0);
    hgemm<2><<<dim3(D_DIM / 128, Th / 128), 128, SMEM_SZ, sC>>>(
        hs + (size_t)Th * ISH, bdsh, 0, out + (size_t)Th * D_DIM, nullptr,
        nullptr, nullptr, sgate + Th, nullptr, ISH, D_DIM);
    if (ok) cudaEventRecord(s_evC, sC);
    hgemm<2><<<dim3(D_DIM / 128, HTILES), 128, SMEM_SZ>>>(
        hh, bd, (long long)D_DIM * IMOE, out, nullptr,
        nullptr, gtok, roww, tileE, IMOE, D_DIM);
    if (ok) cudaStreamWaitEvent(sB, s_evZ, 0);
    hgemm<2><<<dim3(D_DIM / 128, HTILES), 128, SMEM_SZ, sB>>>(
        hh + (size_t)HTILES * 128 * IMOE, bd, (long long)D_DIM * IMOE, out, nullptr,
        nullptr, gtok + HTILES * 128, roww + HTILES * 128, tileE + HTILES,
        IMOE, D_DIM);
    if (ok) cudaEventRecord(s_evB, sB);

    // ---- join back to s0 (graph-capture requires rejoining side streams) ----
    if (ok) {
        cudaStreamWaitEvent(0, s_evA, 0);
        cudaStreamWaitEvent(0, s_evB, 0);
        cudaStreamWaitEvent(0, s_evC, 0);
    }
    fin_kernel<<<1, 32>>>();
}